// round 1
// baseline (speedup 1.0000x reference)
#include <cuda_runtime.h>
#include <cuda_bf16.h>
#include <math.h>

// Problem constants (from reference_code)
#define BATCH      8
#define NPTS       16384
#define NUM_CLASS  100
#define CONVEX_K   10
#define MSKEL      (NUM_CLASS * CONVEX_K)   // 1000
#define NGROUP     (BATCH * NUM_CLASS)      // 800
#define CHAM_BLOCKS_PER_B 32                // 512 points per block
#define CHAM_THREADS      256
#define CHAM_TOTAL_BLOCKS (BATCH * CHAM_BLOCKS_PER_B)  // 256

// ---------------- device scratch (no dynamic allocation allowed) ------------
__device__ unsigned int g_skel_min[BATCH * MSKEL];   // per-(b,m) min d2 as uint bits
__device__ float        g_group_convex[NGROUP];      // per-group convex contributions
__device__ double       g_block_cd[CHAM_TOTAL_BLOCKS]; // per-block point-direction sums

// FLT_MAX bit pattern (positive float ordering == uint ordering)
#define FLTMAX_BITS 0x7F7FFFFFu

// ============================================================================
// Kernel 1: convex-hull loss per group + init of g_skel_min
// 800 threads: one group each. Also each thread initializes 10 skel-min slots.
// ============================================================================
__global__ void convex_init_kernel(const float* __restrict__ skel,
                                   const int*   __restrict__ labels)
{
    int g = blockIdx.x * blockDim.x + threadIdx.x;
    if (g >= NGROUP) return;

    // init skel-min scratch (8000 slots, 10 per thread)
    #pragma unroll
    for (int k = 0; k < 10; ++k)
        g_skel_min[g * 10 + k] = FLTMAX_BITS;

    const int b = g / NUM_CLASS;
    const int c = g % NUM_CLASS;
    const float* p  = skel   + (size_t)(b * MSKEL + c * CONVEX_K) * 3;
    const int*   lb = labels + (b * MSKEL + c * CONVEX_K);

    float px[CONVEX_K], py[CONVEX_K], pz[CONVEX_K];
    int   lv[CONVEX_K];
    #pragma unroll
    for (int j = 0; j < CONVEX_K; ++j) {
        px[j] = p[3 * j + 0];
        py[j] = p[3 * j + 1];
        pz[j] = p[3 * j + 2];
        lv[j] = lb[j];
    }

    float acc = 0.0f;
    #pragma unroll
    for (int i = 0; i < CONVEX_K; ++i) {
        float md = 3.0e38f;
        #pragma unroll
        for (int j = 0; j < CONVEX_K; ++j) {
            if (lv[j] == 1) {
                float dx = px[i] - px[j];
                float dy = py[i] - py[j];
                float dz = pz[i] - pz[j];
                float d2 = fmaf(dx, dx, fmaf(dy, dy, dz * dz));
                md = fminf(md, d2);
            }
        }
        md = fminf(md, 100000.0f);   // MINDIS_INIT clamp (also handles "no verts")
        if (lv[i] != 1) acc += md;
    }
    g_group_convex[g] = acc;
}

// ============================================================================
// Kernel 2: Chamfer. grid = (32, 8). 256 threads, 2 points per thread.
// Both min directions computed in one pass over the 1000 skel points.
// ============================================================================
__global__ void __launch_bounds__(CHAM_THREADS)
chamfer_kernel(const float* __restrict__ xyz, const float* __restrict__ skel)
{
    __shared__ float4       s_sk[MSKEL];      // x, y, z, |s|^2   (16 KB)
    __shared__ unsigned int s_bmin[MSKEL];    // per-block m-direction min bits (4 KB)
    __shared__ double       s_warp[CHAM_THREADS / 32];

    const int b    = blockIdx.y;
    const int tile = blockIdx.x;
    const int tid  = threadIdx.x;
    const int lane = tid & 31;

    // cooperative skel load + ss precompute + block-min init
    const float* sb = skel + (size_t)b * MSKEL * 3;
    for (int i = tid; i < MSKEL; i += CHAM_THREADS) {
        float sx = sb[3 * i + 0];
        float sy = sb[3 * i + 1];
        float sz = sb[3 * i + 2];
        s_sk[i]   = make_float4(sx, sy, sz, fmaf(sx, sx, fmaf(sy, sy, sz * sz)));
        s_bmin[i] = FLTMAX_BITS;
    }
    __syncthreads();

    // two points per thread, coalesced-ish (stride-256 split within the tile)
    const int p0 = b * NPTS + tile * 512 + tid;
    const int p1 = p0 + 256;
    const float ax = xyz[(size_t)p0 * 6 + 0];
    const float ay = xyz[(size_t)p0 * 6 + 1];
    const float az = xyz[(size_t)p0 * 6 + 2];
    const float bx = xyz[(size_t)p1 * 6 + 0];
    const float by = xyz[(size_t)p1 * 6 + 1];
    const float bz = xyz[(size_t)p1 * 6 + 2];
    const float pa2 = fmaf(ax, ax, fmaf(ay, ay, az * az));
    const float pb2 = fmaf(bx, bx, fmaf(by, by, bz * bz));

    float amin = 3.0e38f;   // min over m of (|s|^2 - 2 p_a . s)   ("e-space")
    float bmin = 3.0e38f;

    for (int mc = 0; mc < MSKEL; mc += 10) {
        float mm[10];
        #pragma unroll
        for (int j = 0; j < 10; ++j) {
            const float4 s = s_sk[mc + j];
            float dota = fmaf(ax, s.x, fmaf(ay, s.y, az * s.z));
            float ea   = fmaf(dota, -2.0f, s.w);
            amin = fminf(amin, ea);
            float dotb = fmaf(bx, s.x, fmaf(by, s.y, bz * s.z));
            float eb   = fmaf(dotb, -2.0f, s.w);
            bmin = fminf(bmin, eb);
            mm[j] = fminf(ea + pa2, eb + pb2);   // actual d2 for m-direction
        }
        // warp butterfly min per m, then one smem atomic per warp
        #pragma unroll
        for (int j = 0; j < 10; ++j) {
            float v = mm[j];
            v = fminf(v, __shfl_xor_sync(0xffffffffu, v, 16));
            v = fminf(v, __shfl_xor_sync(0xffffffffu, v, 8));
            v = fminf(v, __shfl_xor_sync(0xffffffffu, v, 4));
            v = fminf(v, __shfl_xor_sync(0xffffffffu, v, 2));
            v = fminf(v, __shfl_xor_sync(0xffffffffu, v, 1));
            if (lane == 0)
                atomicMin(&s_bmin[mc + j], __float_as_uint(fmaxf(v, 0.0f)));
        }
    }
    __syncthreads();

    // publish block mins to global (exact min => deterministic)
    for (int i = tid; i < MSKEL; i += CHAM_THREADS)
        atomicMin(&g_skel_min[b * MSKEL + i], s_bmin[i]);

    // point-direction: finalize d = sqrt(max(d2,1e-12)), block-sum (fixed order)
    float da = sqrtf(fmaxf(amin + pa2, 1e-12f));
    float db = sqrtf(fmaxf(bmin + pb2, 1e-12f));
    double t = (double)da + (double)db;
    #pragma unroll
    for (int off = 16; off > 0; off >>= 1)
        t += __shfl_down_sync(0xffffffffu, t, off);
    if (lane == 0) s_warp[tid >> 5] = t;
    __syncthreads();
    if (tid == 0) {
        double s = 0.0;
        #pragma unroll
        for (int w = 0; w < CHAM_THREADS / 32; ++w) s += s_warp[w];
        g_block_cd[blockIdx.y * gridDim.x + blockIdx.x] = s;
    }
}

// ============================================================================
// Kernel 3: finalize — sum skel-direction sqrts, block sums, convex, combine.
// ============================================================================
__global__ void finalize_kernel(float* __restrict__ out)
{
    __shared__ double s_red[256];
    const int tid = threadIdx.x;

    double cd = 0.0;
    for (int i = tid; i < BATCH * MSKEL; i += 256) {
        float d2 = __uint_as_float(g_skel_min[i]);
        cd += (double)sqrtf(fmaxf(d2, 1e-12f));
    }
    cd += g_block_cd[tid];   // 256 slots, exactly one per thread

    double cv = 0.0;
    for (int i = tid; i < NGROUP; i += 256)
        cv += (double)g_group_convex[i];

    double total = cv * (1.0 / (double)NGROUP) + cd * (0.1 / (double)BATCH);
    s_red[tid] = total;
    __syncthreads();
    for (int s = 128; s > 0; s >>= 1) {
        if (tid < s) s_red[tid] += s_red[tid + s];
        __syncthreads();
    }
    if (tid == 0) out[0] = (float)s_red[0];
}

// ============================================================================
extern "C" void kernel_launch(void* const* d_in, const int* in_sizes, int n_in,
                              void* d_out, int out_size)
{
    const float* xyz    = (const float*)d_in[0];   // [8,16384,6]
    const float* skel   = (const float*)d_in[1];   // [8,1000,3]
    // d_in[2] = weights (unused by reference)
    const int*   labels = (const int*)d_in[3];     // [8,100,10] int32
    float* out = (float*)d_out;

    convex_init_kernel<<<25, 32>>>(skel, labels);
    dim3 grid(CHAM_BLOCKS_PER_B, BATCH);
    chamfer_kernel<<<grid, CHAM_THREADS>>>(xyz, skel);
    finalize_kernel<<<1, 256>>>(out);
}

// round 2
// speedup vs baseline: 2.0690x; 2.0690x over previous
#include <cuda_runtime.h>
#include <cuda_bf16.h>
#include <math.h>

// Problem constants (from reference_code)
#define BATCH      8
#define NPTS       16384
#define NUM_CLASS  100
#define CONVEX_K   10
#define MSKEL      (NUM_CLASS * CONVEX_K)   // 1000
#define MPAIRS     (MSKEL / 2)              // 500 packed m-pairs
#define NGROUP     (BATCH * NUM_CLASS)      // 800

#define TILE_PTS   256
#define CTH        128                      // threads per chamfer block
#define TILES_PER_B (NPTS / TILE_PTS)       // 64
#define CHAM_TOTAL_BLOCKS (BATCH * TILES_PER_B)  // 512

// ---------------- device scratch (no dynamic allocation allowed) ------------
__device__ unsigned int g_skel_min[BATCH * MSKEL];      // per-(b,m) min d2 bits
__device__ float        g_group_convex[NGROUP];         // per-group convex sums
__device__ double       g_block_cd[CHAM_TOTAL_BLOCKS];  // per-block point-dir sums

#define FLTMAX_BITS 0x7F7FFFFFu
#define BIGF 3.0e38f

// ---------------- packed f32x2 helpers (FFMA2 path, sm_103a) ---------------
typedef unsigned long long ull;

__device__ __forceinline__ ull pk2(float lo, float hi) {
    ull r; asm("mov.b64 %0, {%1,%2};" : "=l"(r) : "f"(lo), "f"(hi)); return r;
}
__device__ __forceinline__ void up2(ull v, float& lo, float& hi) {
    asm("mov.b64 {%0,%1}, %2;" : "=f"(lo), "=f"(hi) : "l"(v));
}
__device__ __forceinline__ ull fma2(ull a, ull b, ull c) {
    ull d; asm("fma.rn.f32x2 %0, %1, %2, %3;" : "=l"(d) : "l"(a), "l"(b), "l"(c));
    return d;
}
__device__ __forceinline__ ull mul2(ull a, ull b) {
    ull d; asm("mul.rn.f32x2 %0, %1, %2;" : "=l"(d) : "l"(a), "l"(b));
    return d;
}

// ============================================================================
// Kernel 1: convex-hull loss per group + init of g_skel_min
// ============================================================================
__global__ void convex_init_kernel(const float* __restrict__ skel,
                                   const int*   __restrict__ labels)
{
    int g = blockIdx.x * blockDim.x + threadIdx.x;
    if (g >= NGROUP) return;

    #pragma unroll
    for (int k = 0; k < 10; ++k)
        g_skel_min[g * 10 + k] = FLTMAX_BITS;

    const int b = g / NUM_CLASS;
    const int c = g % NUM_CLASS;
    const float* p  = skel   + (size_t)(b * MSKEL + c * CONVEX_K) * 3;
    const int*   lb = labels + (b * MSKEL + c * CONVEX_K);

    float px[CONVEX_K], py[CONVEX_K], pz[CONVEX_K];
    int   lv[CONVEX_K];
    #pragma unroll
    for (int j = 0; j < CONVEX_K; ++j) {
        px[j] = p[3 * j + 0];
        py[j] = p[3 * j + 1];
        pz[j] = p[3 * j + 2];
        lv[j] = lb[j];
    }

    float acc = 0.0f;
    #pragma unroll
    for (int i = 0; i < CONVEX_K; ++i) {
        float md = BIGF;
        #pragma unroll
        for (int j = 0; j < CONVEX_K; ++j) {
            if (lv[j] == 1) {
                float dx = px[i] - px[j];
                float dy = py[i] - py[j];
                float dz = pz[i] - pz[j];
                float d2 = fmaf(dx, dx, fmaf(dy, dy, dz * dz));
                md = fminf(md, d2);
            }
        }
        md = fminf(md, 100000.0f);
        if (lv[i] != 1) acc += md;
    }
    g_group_convex[g] = acc;
}

// ============================================================================
// Kernel 2: Chamfer, two transposed register-resident passes, packed f32x2.
// grid = (64, 8), 128 threads. Tile = 256 points, all 1000 skel per block.
// ============================================================================
__global__ void __launch_bounds__(CTH)
chamfer_kernel(const float* __restrict__ xyz, const float* __restrict__ skel)
{
    __shared__ float4 s_skx[MPAIRS];    // (sx0, sx1, sy0, sy1) per m-pair
    __shared__ float4 s_skz[MPAIRS];    // (sz0, sz1, ss0, ss1)
    __shared__ float4 s_ptA[TILE_PTS];  // (x, x, y, y) per point (broadcast)
    __shared__ float4 s_ptB[TILE_PTS];  // (z, z, pp, pp)
    __shared__ double s_red[CTH / 32];

    const int b    = blockIdx.y;
    const int tile = blockIdx.x;
    const int tid  = threadIdx.x;
    const int lane = tid & 31;

    // ---- cooperative skel load: pack adjacent m into f32x2 lanes ----
    const float* sb = skel + (size_t)b * MSKEL * 3;
    for (int i = tid; i < MPAIRS; i += CTH) {
        float ax = sb[6 * i + 0], ay = sb[6 * i + 1], az = sb[6 * i + 2];
        float cx = sb[6 * i + 3], cy = sb[6 * i + 4], cz = sb[6 * i + 5];
        float ssa = fmaf(ax, ax, fmaf(ay, ay, az * az));
        float ssc = fmaf(cx, cx, fmaf(cy, cy, cz * cz));
        s_skx[i] = make_float4(ax, cx, ay, cy);
        s_skz[i] = make_float4(az, cz, ssa, ssc);
    }

    // ---- load this thread's 2 points; stage broadcast tile ----
    const int p0 = b * NPTS + tile * TILE_PTS + tid;
    const int p1 = p0 + CTH;
    const float x0 = xyz[(size_t)p0 * 6 + 0];
    const float y0 = xyz[(size_t)p0 * 6 + 1];
    const float z0 = xyz[(size_t)p0 * 6 + 2];
    const float x1 = xyz[(size_t)p1 * 6 + 0];
    const float y1 = xyz[(size_t)p1 * 6 + 1];
    const float z1 = xyz[(size_t)p1 * 6 + 2];
    const float pp0 = fmaf(x0, x0, fmaf(y0, y0, z0 * z0));
    const float pp1 = fmaf(x1, x1, fmaf(y1, y1, z1 * z1));
    s_ptA[tid]       = make_float4(x0, x0, y0, y0);
    s_ptB[tid]       = make_float4(z0, z0, pp0, pp0);
    s_ptA[tid + CTH] = make_float4(x1, x1, y1, y1);
    s_ptB[tid + CTH] = make_float4(z1, z1, pp1, pp1);
    __syncthreads();

    const ull NEG2 = pk2(-2.0f, -2.0f);

    // =================== Pass A: point-direction min ===================
    // min over m of (|s|^2 - 2 p.s), m packed two-at-a-time
    {
        const ull px0 = pk2(x0, x0), py0 = pk2(y0, y0), pz0 = pk2(z0, z0);
        const ull px1 = pk2(x1, x1), py1 = pk2(y1, y1), pz1 = pk2(z1, z1);
        float m0a = BIGF, m0b = BIGF, m1a = BIGF, m1b = BIGF;

        #pragma unroll 4
        for (int i = 0; i < MPAIRS; ++i) {
            const float4 sx = s_skx[i];
            const float4 sz = s_skz[i];
            const ull sxx = pk2(sx.x, sx.y);
            const ull syy = pk2(sx.z, sx.w);
            const ull szz = pk2(sz.x, sz.y);
            const ull sss = pk2(sz.z, sz.w);

            ull d0 = fma2(px0, sxx, fma2(py0, syy, mul2(pz0, szz)));
            ull e0 = fma2(d0, NEG2, sss);
            float ea, eb; up2(e0, ea, eb);
            m0a = fminf(m0a, ea); m0b = fminf(m0b, eb);

            ull d1 = fma2(px1, sxx, fma2(py1, syy, mul2(pz1, szz)));
            ull e1 = fma2(d1, NEG2, sss);
            up2(e1, ea, eb);
            m1a = fminf(m1a, ea); m1b = fminf(m1b, eb);
        }
        float dA = sqrtf(fmaxf(fminf(m0a, m0b) + pp0, 1e-12f));
        float dB = sqrtf(fmaxf(fminf(m1a, m1b) + pp1, 1e-12f));
        double t = (double)dA + (double)dB;
        #pragma unroll
        for (int off = 16; off > 0; off >>= 1)
            t += __shfl_down_sync(0xffffffffu, t, off);
        if (lane == 0) s_red[tid >> 5] = t;
    }

    // =================== Pass B: skel-direction min ===================
    // thread owns 8 m (4 packed pairs); loop over the 256-point tile
    {
        const int ibase = 4 * tid;   // m-pair base index
        ull msx[4], msy[4], msz[4];
        float mss[8];
        float bm[8];
        #pragma unroll
        for (int k = 0; k < 4; ++k) {
            int i = ibase + k;
            if (i < MPAIRS) {
                float4 sx = s_skx[i], sz = s_skz[i];
                msx[k] = pk2(sx.x, sx.y);
                msy[k] = pk2(sx.z, sx.w);
                msz[k] = pk2(sz.x, sz.y);
                mss[2 * k] = sz.z; mss[2 * k + 1] = sz.w;
            } else {
                msx[k] = 0; msy[k] = 0; msz[k] = 0;
                mss[2 * k] = 0.0f; mss[2 * k + 1] = 0.0f;
            }
            bm[2 * k] = BIGF; bm[2 * k + 1] = BIGF;
        }

        #pragma unroll 4
        for (int p = 0; p < TILE_PTS; ++p) {
            const float4 A  = s_ptA[p];   // (x,x,y,y) broadcast
            const float4 Bq = s_ptB[p];   // (z,z,pp,pp)
            const ull pxx = pk2(A.x, A.y);
            const ull pyy = pk2(A.z, A.w);
            const ull pzz = pk2(Bq.x, Bq.y);
            const ull ppp = pk2(Bq.z, Bq.w);
            #pragma unroll
            for (int k = 0; k < 4; ++k) {
                ull d = fma2(msx[k], pxx, fma2(msy[k], pyy, mul2(msz[k], pzz)));
                ull e = fma2(d, NEG2, ppp);        // pp - 2 p.s
                float ea, eb; up2(e, ea, eb);
                bm[2 * k]     = fminf(bm[2 * k],     ea);
                bm[2 * k + 1] = fminf(bm[2 * k + 1], eb);
            }
        }

        if (ibase < MPAIRS) {   // tid < 125: all 8 owned m are valid
            #pragma unroll
            for (int k = 0; k < 8; ++k) {
                int m = 8 * tid + k;
                float d2 = fmaxf(bm[k] + mss[k], 0.0f);
                atomicMin(&g_skel_min[b * MSKEL + m], __float_as_uint(d2));
            }
        }
    }

    // ---- block point-direction sum (fixed order => deterministic) ----
    __syncthreads();
    if (tid == 0) {
        double s = 0.0;
        #pragma unroll
        for (int w = 0; w < CTH / 32; ++w) s += s_red[w];
        g_block_cd[blockIdx.y * gridDim.x + blockIdx.x] = s;
    }
}

// ============================================================================
// Kernel 3: finalize — skel-direction sqrts + block sums + convex, combine.
// ============================================================================
__global__ void finalize_kernel(float* __restrict__ out)
{
    __shared__ double s_red[256];
    const int tid = threadIdx.x;

    double cd = 0.0;
    for (int i = tid; i < BATCH * MSKEL; i += 256) {
        float d2 = __uint_as_float(g_skel_min[i]);
        cd += (double)sqrtf(fmaxf(d2, 1e-12f));
    }
    cd += g_block_cd[tid];          // 512 block slots, 2 per thread
    cd += g_block_cd[tid + 256];

    double cv = 0.0;
    for (int i = tid; i < NGROUP; i += 256)
        cv += (double)g_group_convex[i];

    double total = cv * (1.0 / (double)NGROUP) + cd * (0.1 / (double)BATCH);
    s_red[tid] = total;
    __syncthreads();
    for (int s = 128; s > 0; s >>= 1) {
        if (tid < s) s_red[tid] += s_red[tid + s];
        __syncthreads();
    }
    if (tid == 0) out[0] = (float)s_red[0];
}

// ============================================================================
extern "C" void kernel_launch(void* const* d_in, const int* in_sizes, int n_in,
                              void* d_out, int out_size)
{
    const float* xyz    = (const float*)d_in[0];   // [8,16384,6]
    const float* skel   = (const float*)d_in[1];   // [8,1000,3]
    // d_in[2] = weights (unused by reference)
    const int*   labels = (const int*)d_in[3];     // [8,100,10] int32
    float* out = (float*)d_out;

    convex_init_kernel<<<25, 32>>>(skel, labels);
    dim3 grid(TILES_PER_B, BATCH);
    chamfer_kernel<<<grid, CTH>>>(xyz, skel);
    finalize_kernel<<<1, 256>>>(out);
}